// round 1
// baseline (speedup 1.0000x reference)
#include <cuda_runtime.h>

#define NDIM 2048
#define BKS 32          // blocks (strips)
#define RPB 64          // rows per block (2 per lane)
#define NSTEPS 2112     // 2111 real steps, padded to multiple of 8
#define NEGF (-1e10f)
#define BPAD 96

// boundary rows: g_bnd[b][j] = V[64*(b+1)][j], j in [1,2048]
__device__ float g_bnd[BKS][NDIM + 1 + BPAD];
__device__ int   g_prog[BKS * 32];   // padded; [b*32] = highest boundary col published by block b

__global__ void nw_init() {
    int i = threadIdx.x;
    if (i < BKS) g_prog[i * 32] = 0;
}

__device__ __forceinline__ float ex2f_(float x) {
    float r; asm("ex2.approx.f32 %0, %1;" : "=f"(r) : "f"(x)); return r;
}
__device__ __forceinline__ float lg2f_(float x) {
    float r; asm("lg2.approx.f32 %0, %1;" : "=f"(r) : "f"(x)); return r;
}
__device__ __forceinline__ int ld_acq(const int* p) {
    int v; asm volatile("ld.acquire.gpu.global.b32 %0, [%1];" : "=r"(v) : "l"(p) : "memory");
    return v;
}
// Predicated (branch-free) producer publish: weak store of the boundary value,
// then release store of the progress counter (release orders the prior store).
__device__ __forceinline__ void prod_store(float* bp, int* pp, float v, int j, int flag) {
    asm volatile(
        "{\n\t"
        ".reg .pred p;\n\t"
        "setp.ne.s32 p, %4, 0;\n\t"
        "@p st.global.f32 [%0], %2;\n\t"
        "@p st.release.gpu.global.b32 [%1], %3;\n\t"
        "}"
        :: "l"(bp), "l"(pp), "f"(v), "r"(j), "r"(flag) : "memory");
}

// Exact LSE3 with true max; one exp is exp(0)=1 (folded), so 2 EX2 + 1 LG2.
__device__ __forceinline__ float lse_cell(float up, float dg, float lf,
                                          float A, float th, bool valid) {
    const float L2E = 1.4426950408889634f;
    const float LN2 = 0.6931471805599453f;
    float x  = up + A;           // late arrival (via shuffle / boundary)
    float y  = lf + A;           // own register, early
    float m  = dg;               // own/prev-prev, early
    float w1 = fmaxf(m, y);      // early pre-reduction
    float w2 = fminf(m, y);
    float Mx  = fmaxf(w1, x);                 // max3
    float mid = fmaxf(fminf(x, w1), w2);      // median3
    float lo  = fminf(x, w2);                 // min3
    float s = ex2f_((mid - Mx) * L2E) + ex2f_((lo - Mx) * L2E);
    float v = fmaf(lg2f_(1.0f + s), LN2, Mx + th);
    return valid ? v : NEGF;
}

__global__ void __launch_bounds__(32, 1)
nw_main(const float* __restrict__ theta, const float* __restrict__ Ap,
        float* __restrict__ out) {
    const int b = blockIdx.x;
    const int t = threadIdx.x;
    const float A = *Ap;
    const int R0 = b * RPB;

    // lane t owns rows r0 = R0+1+2t, r1 = r0+1; theta rows r0-1, r1-1
    const float* th0p = theta + (size_t)(R0 + 2 * t) * NDIM;
    const float* th1p = th0p + NDIM;

    float v0m1 = NEGF, v0m2 = NEGF, v1m1 = NEGF;   // own-cell history
    float sh_prev = NEGF;                          // lane t-1's v1 at diag d-2
    float bUprev = (b == 0) ? 0.0f : NEGF;         // V[R0, j0-1]; V[0,0]=0 for b==0

    int*        progp = &g_prog[(b > 0 ? b - 1 : 0) * 32];
    const float* bndp = g_bnd[b > 0 ? b - 1 : 0];
    float*       bout = g_bnd[b];
    int*       myprog = &g_prog[b * 32];
    const int prodflag_base = (t == 31 && b < BKS - 1) ? 1 : 0;

    int seen = 0;
    const int tq = t & 7;
    float bv_cur = NEGF, bv_nxt = NEGF;
    if (b > 0) {
        // prologue: boundary groups for steps [0,8) and [8,16) -> cols up to 16
        while ((seen = ld_acq(progp)) < 16) { }
        bv_cur = __ldcg(bndp + 1 + tq);
        bv_nxt = __ldcg(bndp + 9 + tq);
    }

    const int c0base = -2 * t;   // theta col for cell0 at step s is s + c0base
    // theta prefetch for s = 0
    int c0i = c0base;
    float th0_c = ((unsigned)c0i < NDIM) ? __ldg(th0p + c0i) : 0.0f;
    float th1_c = ((unsigned)(c0i - 1) < NDIM) ? __ldg(th1p + c0i - 1) : 0.0f;

    for (int g = 0; g < NSTEPS / 8; ++g) {
        const int sbase = g * 8;
#pragma unroll
        for (int q = 0; q < 8; ++q) {
            const int s = sbase + q;

            float bU = NEGF;
            if (b > 0) bU = __shfl_sync(0xffffffffu, bv_cur, q);
            float sh = __shfl_up_sync(0xffffffffu, v1m1, 1);  // lane t-1's v1 @ d-1
            float up0 = (t == 0) ? bU : sh;
            float dg0 = (t == 0) ? bUprev : sh_prev;

            const int cc0 = s + c0base;                 // theta col of cell0
            const bool valid0 = (unsigned)cc0 < NDIM;   // 1 <= j0 <= 2048
            const bool valid1 = (unsigned)(cc0 - 1) < NDIM;

            float nv0 = lse_cell(up0, dg0, v0m1, A, th0_c, valid0);
            float nv1 = lse_cell(v0m1, v0m2, v1m1, A, th1_c, valid1);

            // theta prefetch for next step (rows are walked sequentially -> L1 hits)
            const int cn = cc0 + 1;
            th0_c = ((unsigned)cn < NDIM) ? __ldg(th0p + cn) : 0.0f;
            th1_c = ((unsigned)(cn - 1) < NDIM) ? __ldg(th1p + cn - 1) : 0.0f;

            v0m2 = v0m1; v0m1 = nv0;
            sh_prev = sh;
            bUprev = bU;

            // producer: lane 31's r1 is this strip's bottom row; col j1 = s-62
            const int j1 = s - 62;
            const int wflag = prodflag_base & (int)((unsigned)(j1 - 1) < NDIM);
            prod_store(bout + j1, myprog, nv1, j1, wflag);
            if (b == BKS - 1 && t == 31 && j1 == NDIM) out[0] = nv1;

            v1m1 = nv1;
        }
        // advance boundary double-buffer (data for group g+2)
        if (b > 0) {
            bv_cur = bv_nxt;
            const int nbase = sbase + 16;
            if (nbase < NSTEPS) {
                const int need = min(nbase + 8, NDIM);
                if (seen < need) {
                    while ((seen = ld_acq(progp)) < need) { }
                }
                bv_nxt = __ldcg(bndp + nbase + 1 + tq);
            }
        }
    }
}

extern "C" void kernel_launch(void* const* d_in, const int* in_sizes, int n_in,
                              void* d_out, int out_size) {
    const float* theta = (const float*)d_in[0];
    const float* A     = (const float*)d_in[1];
    float* out         = (float*)d_out;
    nw_init<<<1, 32>>>();
    nw_main<<<BKS, 32>>>(theta, A, out);
}

// round 2
// speedup vs baseline: 2.9209x; 2.9209x over previous
#include <cuda_runtime.h>

#define NDIM 2048
#define BKS 32              // blocks (strips of 64 rows)
#define NSTEPS 2112         // per-strip wavefront steps, multiple of 8
#define NGROUPS (NSTEPS/8)  // 264
#define NEGF (-1.4426950e10f)   // -1e10 in log2 domain (scaled)
#define L2E 1.4426950408889634f
#define LN2 0.6931471805599453f

// boundary rows in log2 domain: producer stores cols j1 = 8g-62 .. 8g-55
// front pad 66 so the first store index is 66-62=4 floats -> 16B aligned
#define BOFF 66
#define BLEN 2196           // multiple of 4; max read idx 66+2112=2178, max store 66+2049=2115

__device__ __align__(16) float g_bnd[BKS][BLEN];
__device__ int g_prog[BKS * 32];   // [b*32] = number of groups published by block b

__global__ void nw_init() {
    int i = threadIdx.x;
    if (i < BKS) g_prog[i * 32] = 0;
}

__device__ __forceinline__ float ex2f_(float x) {
    float r; asm("ex2.approx.f32 %0, %1;" : "=f"(r) : "f"(x)); return r;
}
__device__ __forceinline__ float lg2f_(float x) {
    float r; asm("lg2.approx.f32 %0, %1;" : "=f"(r) : "f"(x)); return r;
}
__device__ __forceinline__ int ld_acq(const int* p) {
    int v; asm volatile("ld.acquire.gpu.global.b32 %0, [%1];" : "=r"(v) : "l"(p) : "memory");
    return v;
}

// Per-group publish: 8 boundary floats (two v4 stores) + release counter.
// Predicated inside asm (only lane 31 of non-last blocks fires) -> no divergence.
__device__ __forceinline__ void publish(float* dst, int* pp,
                                        float a0, float a1, float a2, float a3,
                                        float a4, float a5, float a6, float a7,
                                        int cnt, int flag) {
    asm volatile(
        "{\n\t"
        ".reg .pred p;\n\t"
        "setp.ne.s32 p, %11, 0;\n\t"
        "@p st.global.v4.f32 [%0], {%2, %3, %4, %5};\n\t"
        "@p st.global.v4.f32 [%0+16], {%6, %7, %8, %9};\n\t"
        "@p st.release.gpu.global.b32 [%1], %10;\n\t"
        "}"
        :: "l"(dst), "l"(pp),
           "f"(a0), "f"(a1), "f"(a2), "f"(a3),
           "f"(a4), "f"(a5), "f"(a6), "f"(a7),
           "r"(cnt), "r"(flag) : "memory");
}

// log2-domain smoothed max: v' = th' + Mx + log2(1 + 2^(mid-Mx) + 2^(lo-Mx))
__device__ __forceinline__ float lse2(float up, float dg, float lf,
                                      float A2, float th2) {
    float x  = up + A2;
    float y  = lf + A2;
    float w1 = fmaxf(dg, y);
    float w2 = fminf(dg, y);
    float Mx  = fmaxf(w1, x);
    float mid = fmaxf(fminf(x, w1), w2);
    float lo  = fminf(x, w2);
    float s = ex2f_(mid - Mx) + ex2f_(lo - Mx);
    return th2 + Mx + lg2f_(1.0f + s);
}

// Load 8 theta values (cols c..c+7, c even) as 4 aligned float2, scaled to log2 domain.
__device__ __forceinline__ void ldwin(const float* rp, int c, float* w) {
#pragma unroll
    for (int k = 0; k < 8; k += 2) {
        int cc = c + k;
        float2 v = make_float2(0.0f, 0.0f);
        if ((unsigned)cc < NDIM) v = *(const float2*)(rp + cc);
        w[k]   = v.x * L2E;
        w[k+1] = v.y * L2E;
    }
}

__global__ void __launch_bounds__(32, 1)
nw_main(const float* __restrict__ theta, const float* __restrict__ Ap,
        float* __restrict__ out) {
    const int b = blockIdx.x;
    const int t = threadIdx.x;
    const float A2 = (*Ap) * L2E;
    const int R0 = b * 64;

    // lane t owns rows r0 = R0+1+2t, r1 = r0+1 ; theta rows R0+2t, R0+2t+1
    const float* th0p = theta + (size_t)(R0 + 2 * t) * NDIM;
    const float* th1p = th0p + NDIM;

    float v0m1 = NEGF, v0m2 = NEGF, v1m1 = NEGF;
    float sh_prev = NEGF;
    float bUprev = (b == 0) ? 0.0f : NEGF;   // V[R0, j0-1]; V[0,0]=0 for b==0
    float outv = NEGF;

    float*       bout   = g_bnd[b] + BOFF;
    int*         myprog = &g_prog[b * 32];
    const float* bndp   = g_bnd[b > 0 ? b - 1 : 0] + BOFF;
    int*         progp  = &g_prog[(b > 0 ? b - 1 : 0) * 32];
    const int prodflag = (t == 31 && b < BKS - 1) ? 1 : 0;

    // theta windows: current group + next group, prefetched a full group ahead
    const int c0base = -2 * t;
    float w0c[8], w1c[8], w0n[8], w1n[8];
    ldwin(th0p, c0base,     w0c);
    ldwin(th1p, c0base,     w1c);
    ldwin(th0p, c0base + 8, w0n);
    ldwin(th1p, c0base + 8, w1n);
    float th1carry = 0.0f;   // row1 col (c0base-1) is OOB -> 0

    // boundary consumer prologue: need cols 1..16 -> producer groups 0..9 done
    int seen = 0;
    const int tq = t & 7;
    float bv_cur = NEGF, bv_nxt = NEGF;
    if (b > 0) {
        while ((seen = ld_acq(progp)) < 10) { }
        bv_cur = __ldcg(bndp + 1 + tq);
        bv_nxt = __ldcg(bndp + 9 + tq);
    }

    for (int g = 0; g < NGROUPS; ++g) {
        const int sbase = g * 8;
        float pb0, pb1, pb2, pb3, pb4, pb5, pb6, pb7;
#pragma unroll
        for (int q = 0; q < 8; ++q) {
            const int s = sbase + q;
            float bU = (b > 0) ? __shfl_sync(0xffffffffu, bv_cur, q) : NEGF;
            float sh = __shfl_up_sync(0xffffffffu, v1m1, 1);
            float up0 = (t == 0) ? bU : sh;
            float dg0 = (t == 0) ? bUprev : sh_prev;
            float th0 = w0c[q];
            float th1 = (q == 0) ? th1carry : w1c[q - 1];

            float nv0 = lse2(up0, dg0, v0m1, A2, th0);
            float nv1 = lse2(v0m1, v0m2, v1m1, A2, th1);

            v0m2 = v0m1; v0m1 = nv0;
            sh_prev = sh; bUprev = bU;
            v1m1 = nv1;

            if (q == 0) pb0 = nv1; else if (q == 1) pb1 = nv1;
            else if (q == 2) pb2 = nv1; else if (q == 3) pb3 = nv1;
            else if (q == 4) pb4 = nv1; else if (q == 5) pb5 = nv1;
            else if (q == 6) pb6 = nv1; else pb7 = nv1;
            if (s == 2110) outv = nv1;   // V[2048, 2048] (lane31 of last block)
        }

        // producer publish: this group's bottom-row cols j1 = sbase-62 .. sbase-55
        publish(bout + (sbase - 62), myprog,
                pb0, pb1, pb2, pb3, pb4, pb5, pb6, pb7, g + 1, prodflag);

        // consumer: rotate double buffer, wait for the group covering col sbase+24
        if (b > 0) {
            bv_cur = bv_nxt;
            const int nbase = sbase + 16;
            if (nbase < NSTEPS) {
                const int gneed = min(g + 11, NGROUPS);
                if (seen < gneed) {
                    while ((seen = ld_acq(progp)) < gneed) { }
                }
                bv_nxt = __ldcg(bndp + nbase + 1 + tq);
            }
        }

        // rotate theta windows and prefetch group g+2
        th1carry = w1c[7];
#pragma unroll
        for (int k = 0; k < 8; ++k) { w0c[k] = w0n[k]; w1c[k] = w1n[k]; }
        const int cpre = c0base + (g + 2) * 8;
        if (g + 2 < NGROUPS) {
            ldwin(th0p, cpre, w0n);
            ldwin(th1p, cpre, w1n);
        }
    }

    if (b == BKS - 1 && t == 31) out[0] = outv * LN2;  // back to natural log domain
}

extern "C" void kernel_launch(void* const* d_in, const int* in_sizes, int n_in,
                              void* d_out, int out_size) {
    const float* theta = (const float*)d_in[0];
    const float* A     = (const float*)d_in[1];
    float* out         = (float*)d_out;
    nw_init<<<1, 32>>>();
    nw_main<<<BKS, 32>>>(theta, A, out);
}